// round 1
// baseline (speedup 1.0000x reference)
#include <cuda_runtime.h>
#include <cuda_bf16.h>

#define NNODES 50000
#define NEDGES 1600000
#define FN 92
#define FE 41
#define CH 128
#define NL 3
#define NG 256

// -------- scratch (static device globals; allocation-free) --------
__device__ __align__(16) float d_h[NNODES * CH];        // node hidden state
__device__ __align__(16) float d_P[NNODES * 4 * CH];    // [Pfi|Pfj|Psi|Psj]
__device__ __align__(16) float d_agg[NNODES * CH];      // edge aggregation
__device__ __align__(16) float d_h2[NNODES * CH];       // post-FC output
__device__ float d_pool[NG];
__device__ float d_cnt[NG];

__device__ __forceinline__ float softplus_f(float x) {
    // log1p(exp(x)) = max(x,0) + log(1 + exp(-|x|))
    return fmaxf(x, 0.f) + __logf(1.f + __expf(-fabsf(x)));
}
__device__ __forceinline__ float sigmoid_f(float x) {
    return __fdividef(1.f, 1.f + __expf(-x));
}

// -------- generic tiled GEMM: C[M,Nc] = A[M,K] @ B[Nc,K]^T (+bias, +softplus) --------
template <int ACT>
__global__ void gemm_kernel(const float* __restrict__ A, int lda,
                            const float* __restrict__ B, int ldb,
                            const float* __restrict__ bias,
                            float* __restrict__ C, int ldc,
                            int M, int Nc, int K) {
    __shared__ float As[16][65];
    __shared__ float Bs[16][65];
    const int tx = threadIdx.x & 15, ty = threadIdx.x >> 4;
    const int m0 = blockIdx.y * 64, n0 = blockIdx.x * 64;
    float acc[4][4] = {};
    for (int k0 = 0; k0 < K; k0 += 16) {
        for (int idx = threadIdx.x; idx < 64 * 16; idx += 256) {
            int r = idx >> 4, c = idx & 15;
            int m = m0 + r, k = k0 + c, n = n0 + r;
            As[c][r] = (m < M && k < K) ? A[m * lda + k] : 0.f;
            Bs[c][r] = (n < Nc && k < K) ? B[n * ldb + k] : 0.f;
        }
        __syncthreads();
#pragma unroll
        for (int kk = 0; kk < 16; kk++) {
            float a[4], b[4];
#pragma unroll
            for (int i = 0; i < 4; i++) a[i] = As[kk][ty * 4 + i];
#pragma unroll
            for (int j = 0; j < 4; j++) b[j] = Bs[kk][tx * 4 + j];
#pragma unroll
            for (int i = 0; i < 4; i++)
#pragma unroll
                for (int j = 0; j < 4; j++) acc[i][j] += a[i] * b[j];
        }
        __syncthreads();
    }
#pragma unroll
    for (int i = 0; i < 4; i++) {
        int m = m0 + ty * 4 + i;
        if (m >= M) continue;
#pragma unroll
        for (int j = 0; j < 4; j++) {
            int n = n0 + tx * 4 + j;
            if (n >= Nc) continue;
            float v = acc[i][j] + (bias ? bias[n] : 0.f);
            if (ACT) v = softplus_f(v);
            C[m * ldc + n] = v;
        }
    }
}

// -------- edge kernel: gate * softplus message + scatter-add --------
// One thread = one channel; block of 128 threads processes tiles of 32 edges.
// Per-channel edge-projection weights live in registers; ea staged in smem.
__global__ __launch_bounds__(128)
void edge_kernel(const float* __restrict__ P,
                 const float* __restrict__ ea,
                 const int* __restrict__ srcArr,
                 const int* __restrict__ dstArr,
                 const float* __restrict__ Wf,  // layer base [CH,297]
                 const float* __restrict__ Ws,
                 const float* __restrict__ bf,
                 const float* __restrict__ bs,
                 float* __restrict__ agg) {
    const int c = threadIdx.x;
    float wf[44], ws[44];
#pragma unroll
    for (int k = 0; k < 44; k++) {
        wf[k] = (k < FE) ? Wf[c * 297 + 2 * CH + k] : 0.f;
        ws[k] = (k < FE) ? Ws[c * 297 + 2 * CH + k] : 0.f;
    }
    const float bfc = bf[c], bsc = bs[c];

    __shared__ __align__(16) float sEA[32 * 44];
    __shared__ int sSrc[32], sDst[32];

    const int numTiles = (NEDGES + 31) / 32;
    for (int tile = blockIdx.x; tile < numTiles; tile += gridDim.x) {
        const int e0 = tile * 32;
        const int cnt = min(32, NEDGES - e0);
        __syncthreads();
        for (int idx = threadIdx.x; idx < cnt * FE; idx += 128) {
            int e = idx / FE, k = idx - e * FE;
            sEA[e * 44 + k] = ea[(e0 + e) * FE + k];
        }
        for (int idx = threadIdx.x; idx < cnt * 3; idx += 128) {
            int e = idx / 3, k = FE + (idx - e * 3);
            sEA[e * 44 + k] = 0.f;
        }
        if (threadIdx.x < cnt) {
            sSrc[threadIdx.x] = srcArr[e0 + threadIdx.x];
            sDst[threadIdx.x] = dstArr[e0 + threadIdx.x];
        }
        __syncthreads();
        for (int e = 0; e < cnt; e++) {
            const int s = sSrc[e], d = sDst[e];
            // gathers issued early; consumed after the FMA loop (latency hidden)
            const float gfi = P[d * 512 + c];
            const float gfj = P[s * 512 + CH + c];
            const float gsi = P[d * 512 + 2 * CH + c];
            const float gsj = P[s * 512 + 3 * CH + c];
            float accf = 0.f, accs = 0.f;
            const float4* e4 = reinterpret_cast<const float4*>(&sEA[e * 44]);
#pragma unroll
            for (int k4 = 0; k4 < 11; k4++) {
                float4 q = e4[k4];
                accf += wf[4 * k4 + 0] * q.x; accs += ws[4 * k4 + 0] * q.x;
                accf += wf[4 * k4 + 1] * q.y; accs += ws[4 * k4 + 1] * q.y;
                accf += wf[4 * k4 + 2] * q.z; accs += ws[4 * k4 + 2] * q.z;
                accf += wf[4 * k4 + 3] * q.w; accs += ws[4 * k4 + 3] * q.w;
            }
            const float lf = accf + gfi + gfj + bfc;
            const float ls = accs + gsi + gsj + bsc;
            const float m = sigmoid_f(lf) * softplus_f(ls);
            atomicAdd(&agg[d * CH + c], m);
        }
    }
}

__global__ void node_update_kernel(float* __restrict__ h, float* __restrict__ agg) {
    int i = blockIdx.x * blockDim.x + threadIdx.x;
    if (i < NNODES * CH) {
        h[i] = softplus_f(h[i] + agg[i]);
        agg[i] = 0.f;  // ready for next layer
    }
}

__global__ void zero_kernel(float* __restrict__ p, int n) {
    int i = blockIdx.x * blockDim.x + threadIdx.x;
    if (i < n) p[i] = 0.f;
}

__global__ void zero_pool_kernel(float* __restrict__ pool, float* __restrict__ cnt) {
    int i = threadIdx.x;
    if (i < NG) { pool[i] = 0.f; cnt[i] = 0.f; }
}

// warp per node: dot(h2[n], W_out) then atomic into graph bucket
__global__ void pool_kernel(const float* __restrict__ h2, const int* __restrict__ batch,
                            const float* __restrict__ Wout,
                            float* __restrict__ pool, float* __restrict__ cnt) {
    int n = blockIdx.x * (blockDim.x >> 5) + (threadIdx.x >> 5);
    int lane = threadIdx.x & 31;
    if (n >= NNODES) return;
    float s = 0.f;
#pragma unroll
    for (int c = lane; c < CH; c += 32) s += h2[n * CH + c] * Wout[c];
#pragma unroll
    for (int o = 16; o; o >>= 1) s += __shfl_down_sync(0xffffffffu, s, o);
    if (lane == 0) {
        int b = batch[n];
        atomicAdd(&pool[b], s);
        atomicAdd(&cnt[b], 1.f);
    }
}

__global__ void final_kernel(const float* __restrict__ pool, const float* __restrict__ cnt,
                             const float* __restrict__ bout, float* __restrict__ out) {
    int g = blockIdx.x * blockDim.x + threadIdx.x;
    if (g < NG) out[g] = pool[g] / fmaxf(cnt[g], 1.f) + bout[0];
}

extern "C" void kernel_launch(void* const* d_in, const int* in_sizes, int n_in,
                              void* d_out, int out_size) {
    const float* x      = (const float*)d_in[0];
    const int*   ei     = (const int*)d_in[1];
    const float* ea     = (const float*)d_in[2];
    const int*   batch  = (const int*)d_in[3];
    const float* W_pre  = (const float*)d_in[4];
    const float* b_pre  = (const float*)d_in[5];
    const float* Wf     = (const float*)d_in[6];
    const float* bf     = (const float*)d_in[7];
    const float* Ws     = (const float*)d_in[8];
    const float* bs     = (const float*)d_in[9];
    const float* W_post = (const float*)d_in[10];
    const float* b_post = (const float*)d_in[11];
    const float* W_out  = (const float*)d_in[12];
    const float* b_out  = (const float*)d_in[13];
    float* out = (float*)d_out;

    float *h, *P, *agg, *h2, *pool, *cnt;
    cudaGetSymbolAddress((void**)&h, d_h);
    cudaGetSymbolAddress((void**)&P, d_P);
    cudaGetSymbolAddress((void**)&agg, d_agg);
    cudaGetSymbolAddress((void**)&h2, d_h2);
    cudaGetSymbolAddress((void**)&pool, d_pool);
    cudaGetSymbolAddress((void**)&cnt, d_cnt);

    const int NC = NNODES * CH;

    // init scratch
    zero_kernel<<<(NC + 255) / 256, 256>>>(agg, NC);
    zero_pool_kernel<<<1, 256>>>(pool, cnt);

    // pre-FC: h = softplus(x @ W_pre^T + b_pre)
    {
        dim3 g((CH + 63) / 64, (NNODES + 63) / 64);
        gemm_kernel<1><<<g, 256>>>(x, FN, W_pre, FN, b_pre, h, CH, NNODES, CH, FN);
    }

    for (int l = 0; l < NL; l++) {
        const float* Wf_l = Wf + (size_t)l * CH * 297;
        const float* Ws_l = Ws + (size_t)l * CH * 297;
        dim3 g((CH + 63) / 64, (NNODES + 63) / 64);
        // node projections into P = [Pfi | Pfj | Psi | Psj]
        gemm_kernel<0><<<g, 256>>>(h, CH, Wf_l,        297, nullptr, P + 0 * CH, 4 * CH, NNODES, CH, CH);
        gemm_kernel<0><<<g, 256>>>(h, CH, Wf_l + CH,   297, nullptr, P + 1 * CH, 4 * CH, NNODES, CH, CH);
        gemm_kernel<0><<<g, 256>>>(h, CH, Ws_l,        297, nullptr, P + 2 * CH, 4 * CH, NNODES, CH, CH);
        gemm_kernel<0><<<g, 256>>>(h, CH, Ws_l + CH,   297, nullptr, P + 3 * CH, 4 * CH, NNODES, CH, CH);

        edge_kernel<<<592, 128>>>(P, ea, ei, ei + NEDGES, Wf_l, Ws_l,
                                  bf + l * CH, bs + l * CH, agg);

        node_update_kernel<<<(NC + 255) / 256, 256>>>(h, agg);
    }

    // post-FC
    {
        dim3 g((CH + 63) / 64, (NNODES + 63) / 64);
        gemm_kernel<1><<<g, 256>>>(h, CH, W_post, CH, b_post, h2, CH, NNODES, CH, CH);
    }

    // mean-pool + output head (fused: dot with W_out before pooling)
    pool_kernel<<<(NNODES + 7) / 8, 256>>>(h2, batch, W_out, pool, cnt);
    final_kernel<<<1, 256>>>(pool, cnt, b_out, out);
}

// round 2
// speedup vs baseline: 1.2183x; 1.2183x over previous
#include <cuda_runtime.h>
#include <cuda_bf16.h>

#define NNODES 50000
#define NEDGES 1600000
#define FN 92
#define FE 41
#define CH 128
#define NL 3
#define NG 256

// -------- scratch (static device globals; allocation-free) --------
__device__ __align__(16) float d_h[NNODES * CH];
__device__ __align__(16) float d_P[NNODES * 4 * CH];
__device__ __align__(16) float d_agg[NNODES * CH];
__device__ __align__(16) float d_h2[NNODES * CH];
__device__ __align__(16) float d_Wpack[4 * CH * CH];
__device__ float d_pool[NG];
__device__ float d_cnt[NG];

__device__ __forceinline__ float softplus_f(float x) {
    return fmaxf(x, 0.f) + __logf(1.f + __expf(-fabsf(x)));
}
__device__ __forceinline__ float sigmoid_f(float x) {
    return __fdividef(1.f, 1.f + __expf(-x));
}

// ---- f32x2 packed helpers (Blackwell packed fp32 pipe) ----
__device__ __forceinline__ unsigned long long pack2f(float lo, float hi) {
    unsigned long long r;
    asm("mov.b64 %0, {%1, %2};" : "=l"(r) : "f"(lo), "f"(hi));
    return r;
}
__device__ __forceinline__ unsigned long long ffma2(unsigned long long a,
                                                    unsigned long long b,
                                                    unsigned long long c) {
    unsigned long long r;
    asm("fma.rn.f32x2 %0, %1, %2, %3;" : "=l"(r) : "l"(a), "l"(b), "l"(c));
    return r;
}
__device__ __forceinline__ float sum2f(unsigned long long d) {
    float lo, hi;
    asm("mov.b64 {%0, %1}, %2;" : "=f"(lo), "=f"(hi) : "l"(d));
    return lo + hi;
}

// -------- small 64x64 GEMM (pre/post FC; handles odd K) --------
template <int ACT>
__global__ void gemm_kernel(const float* __restrict__ A, int lda,
                            const float* __restrict__ B, int ldb,
                            const float* __restrict__ bias,
                            float* __restrict__ C, int ldc,
                            int M, int Nc, int K) {
    __shared__ float As[16][65];
    __shared__ float Bs[16][65];
    const int tx = threadIdx.x & 15, ty = threadIdx.x >> 4;
    const int m0 = blockIdx.y * 64, n0 = blockIdx.x * 64;
    float acc[4][4] = {};
    for (int k0 = 0; k0 < K; k0 += 16) {
        for (int idx = threadIdx.x; idx < 64 * 16; idx += 256) {
            int r = idx >> 4, c = idx & 15;
            int m = m0 + r, k = k0 + c, n = n0 + r;
            As[c][r] = (m < M && k < K) ? A[m * lda + k] : 0.f;
            Bs[c][r] = (n < Nc && k < K) ? B[n * ldb + k] : 0.f;
        }
        __syncthreads();
#pragma unroll
        for (int kk = 0; kk < 16; kk++) {
            float a[4], b[4];
#pragma unroll
            for (int i = 0; i < 4; i++) a[i] = As[kk][ty * 4 + i];
#pragma unroll
            for (int j = 0; j < 4; j++) b[j] = Bs[kk][tx * 4 + j];
#pragma unroll
            for (int i = 0; i < 4; i++)
#pragma unroll
                for (int j = 0; j < 4; j++) acc[i][j] += a[i] * b[j];
        }
        __syncthreads();
    }
#pragma unroll
    for (int i = 0; i < 4; i++) {
        int m = m0 + ty * 4 + i;
        if (m >= M) continue;
#pragma unroll
        for (int j = 0; j < 4; j++) {
            int n = n0 + tx * 4 + j;
            if (n >= Nc) continue;
            float v = acc[i][j] + (bias ? bias[n] : 0.f);
            if (ACT) v = softplus_f(v);
            C[m * ldc + n] = v;
        }
    }
}

// -------- big SGEMM: 128x128 tile, BK=8, 8x8/thread (K multiple of 8, Nc mult of 128) --------
__global__ __launch_bounds__(256)
void gemm128_kernel(const float* __restrict__ A, int lda,
                    const float* __restrict__ B, int ldb,
                    float* __restrict__ C, int ldc,
                    int M, int K) {
    __shared__ float As[8][128];
    __shared__ float Bs[8][128];
    const int tid = threadIdx.x;
    const int tx = tid & 15, ty = tid >> 4;
    const int m0 = blockIdx.y * 128, n0 = blockIdx.x * 128;
    const int lrow = tid >> 1;          // 0..127
    const int lk = (tid & 1) * 4;       // 0 or 4
    float acc[8][8] = {};
    for (int k0 = 0; k0 < K; k0 += 8) {
        float4 av = make_float4(0.f, 0.f, 0.f, 0.f);
        if (m0 + lrow < M)
            av = *reinterpret_cast<const float4*>(&A[(size_t)(m0 + lrow) * lda + k0 + lk]);
        float4 bv = *reinterpret_cast<const float4*>(&B[(size_t)(n0 + lrow) * ldb + k0 + lk]);
        As[lk + 0][lrow] = av.x; As[lk + 1][lrow] = av.y;
        As[lk + 2][lrow] = av.z; As[lk + 3][lrow] = av.w;
        Bs[lk + 0][lrow] = bv.x; Bs[lk + 1][lrow] = bv.y;
        Bs[lk + 2][lrow] = bv.z; Bs[lk + 3][lrow] = bv.w;
        __syncthreads();
#pragma unroll
        for (int kk = 0; kk < 8; kk++) {
            float a[8], b[8];
            *reinterpret_cast<float4*>(&a[0]) = *reinterpret_cast<const float4*>(&As[kk][ty * 8]);
            *reinterpret_cast<float4*>(&a[4]) = *reinterpret_cast<const float4*>(&As[kk][ty * 8 + 4]);
            *reinterpret_cast<float4*>(&b[0]) = *reinterpret_cast<const float4*>(&Bs[kk][tx * 8]);
            *reinterpret_cast<float4*>(&b[4]) = *reinterpret_cast<const float4*>(&Bs[kk][tx * 8 + 4]);
#pragma unroll
            for (int i = 0; i < 8; i++)
#pragma unroll
                for (int j = 0; j < 8; j++) acc[i][j] += a[i] * b[j];
        }
        __syncthreads();
    }
#pragma unroll
    for (int i = 0; i < 8; i++) {
        int m = m0 + ty * 8 + i;
        if (m >= M) continue;
#pragma unroll
        for (int j = 0; j < 8; j++)
            C[(size_t)m * ldc + n0 + tx * 8 + j] = acc[i][j];
    }
}

// pack per-layer node-projection weights into [512, 128]
__global__ void pack_w_kernel(const float* __restrict__ Wf, const float* __restrict__ Ws,
                              float* __restrict__ Wp) {
    int i = blockIdx.x * 256 + threadIdx.x;
    if (i >= 512 * 128) return;
    int r = i >> 7, k = i & 127;
    float v;
    if (r < 128)      v = Wf[r * 297 + k];
    else if (r < 256) v = Wf[(r - 128) * 297 + 128 + k];
    else if (r < 384) v = Ws[(r - 256) * 297 + k];
    else              v = Ws[(r - 384) * 297 + 128 + k];
    Wp[i] = v;
}

// -------- edge kernel: f32x2 packed FMAs, gate*softplus, scatter-add --------
__global__ __launch_bounds__(128)
void edge_kernel(const float* __restrict__ P,
                 const float* __restrict__ ea,
                 const int* __restrict__ srcArr,
                 const int* __restrict__ dstArr,
                 const float* __restrict__ Wf,
                 const float* __restrict__ Ws,
                 const float* __restrict__ bf,
                 const float* __restrict__ bs,
                 float* __restrict__ agg) {
    const int c = threadIdx.x;
    unsigned long long wf2[22], ws2[22];
#pragma unroll
    for (int k2 = 0; k2 < 22; k2++) {
        int k0 = 2 * k2, k1 = 2 * k2 + 1;
        float f0 = (k0 < FE) ? Wf[c * 297 + 2 * CH + k0] : 0.f;
        float f1 = (k1 < FE) ? Wf[c * 297 + 2 * CH + k1] : 0.f;
        float s0 = (k0 < FE) ? Ws[c * 297 + 2 * CH + k0] : 0.f;
        float s1 = (k1 < FE) ? Ws[c * 297 + 2 * CH + k1] : 0.f;
        wf2[k2] = pack2f(f0, f1);
        ws2[k2] = pack2f(s0, s1);
    }
    const float bfc = bf[c], bsc = bs[c];

    __shared__ __align__(16) float sEA[32 * 44];
    __shared__ int sSrc[32], sDst[32];

    const int numTiles = (NEDGES + 31) / 32;
    for (int tile = blockIdx.x; tile < numTiles; tile += gridDim.x) {
        const int e0 = tile * 32;
        const int cnt = min(32, NEDGES - e0);
        __syncthreads();
        for (int idx = threadIdx.x; idx < cnt * FE; idx += 128) {
            int e = idx / FE, k = idx - e * FE;
            sEA[e * 44 + k] = ea[(e0 + e) * FE + k];
        }
        for (int idx = threadIdx.x; idx < cnt * 3; idx += 128) {
            int e = idx / 3, k = FE + (idx - e * 3);
            sEA[e * 44 + k] = 0.f;
        }
        if (threadIdx.x < cnt) {
            sSrc[threadIdx.x] = srcArr[e0 + threadIdx.x];
            sDst[threadIdx.x] = dstArr[e0 + threadIdx.x];
        }
        __syncthreads();
        for (int e = 0; e < cnt; e++) {
            const int s = sSrc[e], d = sDst[e];
            const float gfi = P[d * 512 + c];
            const float gfj = P[s * 512 + CH + c];
            const float gsi = P[d * 512 + 2 * CH + c];
            const float gsj = P[s * 512 + 3 * CH + c];
            unsigned long long af = 0ull, as_ = 0ull;
            const ulonglong2* e2 = reinterpret_cast<const ulonglong2*>(&sEA[e * 44]);
#pragma unroll
            for (int k4 = 0; k4 < 11; k4++) {
                ulonglong2 q = e2[k4];
                af  = ffma2(wf2[2 * k4],     q.x, af);
                as_ = ffma2(ws2[2 * k4],     q.x, as_);
                af  = ffma2(wf2[2 * k4 + 1], q.y, af);
                as_ = ffma2(ws2[2 * k4 + 1], q.y, as_);
            }
            const float lf = sum2f(af) + gfi + gfj + bfc;
            const float ls = sum2f(as_) + gsi + gsj + bsc;
            const float m = sigmoid_f(lf) * softplus_f(ls);
            atomicAdd(&agg[d * CH + c], m);
        }
    }
}

__global__ void node_update_kernel(float* __restrict__ h, float* __restrict__ agg) {
    int i = blockIdx.x * blockDim.x + threadIdx.x;
    if (i < NNODES * CH) {
        h[i] = softplus_f(h[i] + agg[i]);
        agg[i] = 0.f;
    }
}

__global__ void zero_kernel(float* __restrict__ p, int n) {
    int i = blockIdx.x * blockDim.x + threadIdx.x;
    if (i < n) p[i] = 0.f;
}

__global__ void zero_pool_kernel(float* __restrict__ pool, float* __restrict__ cnt) {
    int i = threadIdx.x;
    if (i < NG) { pool[i] = 0.f; cnt[i] = 0.f; }
}

__global__ void pool_kernel(const float* __restrict__ h2, const int* __restrict__ batch,
                            const float* __restrict__ Wout,
                            float* __restrict__ pool, float* __restrict__ cnt) {
    int n = blockIdx.x * (blockDim.x >> 5) + (threadIdx.x >> 5);
    int lane = threadIdx.x & 31;
    if (n >= NNODES) return;
    float s = 0.f;
#pragma unroll
    for (int c = lane; c < CH; c += 32) s += h2[n * CH + c] * Wout[c];
#pragma unroll
    for (int o = 16; o; o >>= 1) s += __shfl_down_sync(0xffffffffu, s, o);
    if (lane == 0) {
        int b = batch[n];
        atomicAdd(&pool[b], s);
        atomicAdd(&cnt[b], 1.f);
    }
}

__global__ void final_kernel(const float* __restrict__ pool, const float* __restrict__ cnt,
                             const float* __restrict__ bout, float* __restrict__ out) {
    int g = blockIdx.x * blockDim.x + threadIdx.x;
    if (g < NG) out[g] = pool[g] / fmaxf(cnt[g], 1.f) + bout[0];
}

extern "C" void kernel_launch(void* const* d_in, const int* in_sizes, int n_in,
                              void* d_out, int out_size) {
    const float* x      = (const float*)d_in[0];
    const int*   ei     = (const int*)d_in[1];
    const float* ea     = (const float*)d_in[2];
    const int*   batch  = (const int*)d_in[3];
    const float* W_pre  = (const float*)d_in[4];
    const float* b_pre  = (const float*)d_in[5];
    const float* Wf     = (const float*)d_in[6];
    const float* bf     = (const float*)d_in[7];
    const float* Ws     = (const float*)d_in[8];
    const float* bs     = (const float*)d_in[9];
    const float* W_post = (const float*)d_in[10];
    const float* b_post = (const float*)d_in[11];
    const float* W_out  = (const float*)d_in[12];
    const float* b_out  = (const float*)d_in[13];
    float* out = (float*)d_out;

    float *h, *P, *agg, *h2, *pool, *cnt, *Wp;
    cudaGetSymbolAddress((void**)&h, d_h);
    cudaGetSymbolAddress((void**)&P, d_P);
    cudaGetSymbolAddress((void**)&agg, d_agg);
    cudaGetSymbolAddress((void**)&h2, d_h2);
    cudaGetSymbolAddress((void**)&pool, d_pool);
    cudaGetSymbolAddress((void**)&cnt, d_cnt);
    cudaGetSymbolAddress((void**)&Wp, d_Wpack);

    const int NC = NNODES * CH;

    zero_kernel<<<(NC + 255) / 256, 256>>>(agg, NC);
    zero_pool_kernel<<<1, 256>>>(pool, cnt);

    // pre-FC
    {
        dim3 g((CH + 63) / 64, (NNODES + 63) / 64);
        gemm_kernel<1><<<g, 256>>>(x, FN, W_pre, FN, b_pre, h, CH, NNODES, CH, FN);
    }

    for (int l = 0; l < NL; l++) {
        const float* Wf_l = Wf + (size_t)l * CH * 297;
        const float* Ws_l = Ws + (size_t)l * CH * 297;

        pack_w_kernel<<<(512 * 128 + 255) / 256, 256>>>(Wf_l, Ws_l, Wp);

        dim3 g(4, (NNODES + 127) / 128);
        gemm128_kernel<<<g, 256>>>(h, CH, Wp, CH, P, 4 * CH, NNODES, CH);

        edge_kernel<<<592, 128>>>(P, ea, ei, ei + NEDGES, Wf_l, Ws_l,
                                  bf + l * CH, bs + l * CH, agg);

        node_update_kernel<<<(NC + 255) / 256, 256>>>(h, agg);
    }

    // post-FC
    {
        dim3 g((CH + 63) / 64, (NNODES + 63) / 64);
        gemm_kernel<1><<<g, 256>>>(h, CH, W_post, CH, b_post, h2, CH, NNODES, CH, CH);
    }

    pool_kernel<<<(NNODES + 7) / 8, 256>>>(h2, batch, W_out, pool, cnt);
    final_kernel<<<1, 256>>>(pool, cnt, b_out, out);
}